// round 7
// baseline (speedup 1.0000x reference)
#include <cuda_runtime.h>
#include <cuda_bf16.h>
#include <math.h>
#include <stdint.h>

#define U      256
#define BATCHN 32768
#define NL     8
#define INDIM  784
#define ODIM   10
#define KX     832            // INDIM padded to a multiple of 32

// ======================= device memory pool (no allocations) =======================
static constexpr size_t O_XH  = 0;
static constexpr size_t O_XL  = O_XH  + (size_t)BATCHN * KX * 2;
static constexpr size_t O_WTH = O_XL  + (size_t)BATCHN * KX * 2;
static constexpr size_t O_WTL = O_WTH + (size_t)U * KX * 2;
static constexpr size_t O_RH  = O_WTL + (size_t)U * KX * 2;
static constexpr size_t O_RL  = O_RH  + (size_t)BATCHN * 2 * U * 2;
static constexpr size_t O_V1H = O_RL  + (size_t)BATCHN * 2 * U * 2;
static constexpr size_t O_V1L = O_V1H + (size_t)BATCHN * U * 2;
static constexpr size_t O_V0H = O_V1L + (size_t)BATCHN * U * 2;
static constexpr size_t O_V0L = O_V0H + (size_t)BATCHN * U * 2;
static constexpr size_t O_EH  = O_V0L + (size_t)BATCHN * U * 2;
static constexpr size_t O_EL  = O_EH  + (size_t)NL * U * 2 * U * 2;
static constexpr size_t O_BH  = O_EL  + (size_t)NL * U * 2 * U * 2;
static constexpr size_t O_BL  = O_BH  + (size_t)NL * U * U * 2;
static constexpr size_t O_M   = O_BL  + (size_t)NL * U * U * 2;
static constexpr size_t O_XA  = O_M   + (size_t)NL * U * U * 4;
static constexpr size_t O_XB  = O_XA  + (size_t)NL * U * U * 4;
static constexpr size_t O_T   = O_XB  + (size_t)NL * U * U * 4;
static constexpr size_t O_EF  = O_T   + (size_t)NL * U * U * 4;
static constexpr size_t POOLSZ = O_EF + (size_t)NL * U * 2 * U * 4;

__device__ __align__(1024) unsigned char g_pool[POOLSZ];

// ======================= mma.sync helpers (baseline PTX, legal on compute_103) =======
__device__ __forceinline__ void mma16816(float* c, const uint32_t* a, const uint32_t* b) {
    asm volatile(
        "mma.sync.aligned.m16n8k16.row.col.f32.bf16.bf16.f32 "
        "{%0,%1,%2,%3}, {%4,%5,%6,%7}, {%8,%9}, {%0,%1,%2,%3};"
        : "+f"(c[0]), "+f"(c[1]), "+f"(c[2]), "+f"(c[3])
        : "r"(a[0]), "r"(a[1]), "r"(a[2]), "r"(a[3]), "r"(b[0]), "r"(b[1]));
}

__device__ __forceinline__ void ldsm4(uint32_t* r, uint32_t addr) {
    asm volatile("ldmatrix.sync.aligned.m8n8.x4.shared.b16 {%0,%1,%2,%3}, [%4];"
                 : "=r"(r[0]), "=r"(r[1]), "=r"(r[2]), "=r"(r[3]) : "r"(addr));
}

// 64B rows, 4x 16B granules, XOR swizzle keyed on row bits 1-2 -> conflict-free LDSM/STS
__device__ __forceinline__ uint32_t swb(int row, int g) {
    return (uint32_t)(row * 64 + ((g ^ ((row >> 1) & 3)) * 16));
}

__device__ __forceinline__ void cpasync16(uint32_t daddr, const void* src) {
    asm volatile("cp.async.cg.shared.global [%0], [%1], 16;" :: "r"(daddr), "l"(src));
}

// split / merge helpers for bf16-pair fp32 emulation
__device__ __forceinline__ void st2(__nv_bfloat16* h, __nv_bfloat16* l, size_t idx,
                                    float x0, float x1) {
    __nv_bfloat16 h0 = __float2bfloat16(x0);
    __nv_bfloat16 h1 = __float2bfloat16(x1);
    __nv_bfloat162 hv; hv.x = h0; hv.y = h1;
    __nv_bfloat162 lv;
    lv.x = __float2bfloat16(x0 - __bfloat162float(h0));
    lv.y = __float2bfloat16(x1 - __bfloat162float(h1));
    *(__nv_bfloat162*)(h + idx) = hv;
    *(__nv_bfloat162*)(l + idx) = lv;
}

__device__ __forceinline__ void ld2(const __nv_bfloat16* h, const __nv_bfloat16* l, size_t idx,
                                    float& x0, float& x1) {
    __nv_bfloat162 hv = *(const __nv_bfloat162*)(h + idx);
    __nv_bfloat162 lv = *(const __nv_bfloat162*)(l + idx);
    x0 = __bfloat162float(hv.x) + __bfloat162float(lv.x);
    x1 = __bfloat162float(hv.y) + __bfloat162float(lv.y);
}

// ======================= HMMA bf16-split GEMM (cp.async double-buffered) ============
// D[b0..b0+63][0..255] = sum_k A[b][k] * B[n][k]; A/B bf16 hi/lo pairs, fp32 accum,
// 3 products (hh + hl + lh).
// EPI 0: input layer  -> layer-0 R:  r1 = 2*tanh(acc+bias), r0 = acc+bias+0.1*q
// EPI 1: z1 GEMM      -> v1 pair
// EPI 2: z0 GEMM l<7  -> v0 = r0_aux - acc; next R: r1 = v1 + tanh(v0), r0 = v0 + 0.1*q
// EPI 3: z0 GEMM l=7  -> v0 = r0_aux - acc -> v0 pair
#define A_SZ     4096        // 64 rows x 64B
#define B_SZ     16384       // 256 rows x 64B
#define STAGE_SZ (2 * A_SZ + 2 * B_SZ)           // 40 KB
#define SMEM_TOT (2 * STAGE_SZ)                  // 80 KB (double buffer)

__device__ __forceinline__ void load_chunk(
    uint32_t sbase, const __nv_bfloat16* __restrict__ Ah, const __nv_bfloat16* __restrict__ Al,
    const __nv_bfloat16* __restrict__ Bh, const __nv_bfloat16* __restrict__ Bl,
    int lda, int b0, int k0, int tid)
{
    #pragma unroll
    for (int i = tid; i < 2560; i += 128) {
        const __nv_bfloat16* src; uint32_t dst;
        if (i < 512) {
            int part = i >> 8, idx = i & 255, row = idx >> 2, g = idx & 3;
            src = (part ? Al : Ah) + (size_t)(b0 + row) * lda + k0 + g * 8;
            dst = sbase + part * A_SZ + swb(row, g);
        } else {
            int j = i - 512;
            int part = j >> 10, idx = j & 1023, row = idx >> 2, g = idx & 3;
            src = (part ? Bl : Bh) + (size_t)row * lda + k0 + g * 8;
            dst = sbase + 2 * A_SZ + part * B_SZ + swb(row, g);
        }
        cpasync16(dst, src);
    }
    asm volatile("cp.async.commit_group;" ::: "memory");
}

template <int EPI>
__global__ void __launch_bounds__(128, 2)
mmaGemm(const __nv_bfloat16* __restrict__ Ah, const __nv_bfloat16* __restrict__ Al, int lda,
        const __nv_bfloat16* __restrict__ Bh, const __nv_bfloat16* __restrict__ Bl,
        const float* __restrict__ bias, const float* __restrict__ qn,
        const __nv_bfloat16* __restrict__ auxh, const __nv_bfloat16* __restrict__ auxl,
        __nv_bfloat16* __restrict__ Oh, __nv_bfloat16* __restrict__ Ol)
{
    extern __shared__ __align__(128) unsigned char smem[];
    const uint32_t sb = (uint32_t)__cvta_generic_to_shared(smem);

    const int tid  = threadIdx.x;
    const int warp = tid >> 5, lane = tid & 31;
    const int gid  = lane >> 2, tig = lane & 3;
    const int b0   = blockIdx.x * 64;
    const int nb   = warp * 64;                 // warp's N base

    float cfr[4][8][4] = {};                    // [mi][ni][reg]

    const int nchunk = lda >> 5;

    // prologue: prefetch chunk 0 into stage 0
    load_chunk(sb, Ah, Al, Bh, Bl, lda, b0, 0, tid);

    for (int ch = 0; ch < nchunk; ch++) {
        // prefetch next chunk into the other stage
        if (ch + 1 < nchunk)
            load_chunk(sb + ((ch + 1) & 1) * STAGE_SZ, Ah, Al, Bh, Bl,
                       lda, b0, (ch + 1) << 5, tid);

        if (ch + 1 < nchunk) asm volatile("cp.async.wait_group 1;" ::: "memory");
        else                 asm volatile("cp.async.wait_group 0;" ::: "memory");
        __syncthreads();

        const uint32_t st  = sb + (ch & 1) * STAGE_SZ;
        const uint32_t sAh = st, sAl = st + A_SZ;
        const uint32_t sBh = st + 2 * A_SZ, sBl = st + 2 * A_SZ + B_SZ;

        #pragma unroll
        for (int ks = 0; ks < 2; ks++) {
            uint32_t ah[4][4], al[4][4];
            const int arow = (lane & 15);
            const int agr  = ks * 2 + (lane >> 4);
            #pragma unroll
            for (int mi = 0; mi < 4; mi++) {
                uint32_t off = swb(mi * 16 + arow, agr);
                ldsm4(ah[mi], sAh + off);
                ldsm4(al[mi], sAl + off);
            }
            const int brow = (lane & 7) + ((lane >> 4) << 3);
            const int bgr  = ks * 2 + ((lane >> 3) & 1);
            #pragma unroll
            for (int np = 0; np < 4; np++) {            // n-tile pairs (2np, 2np+1)
                uint32_t off = swb(nb + np * 16 + brow, bgr);
                uint32_t bh[4], bl[4];
                ldsm4(bh, sBh + off);
                ldsm4(bl, sBl + off);
                #pragma unroll
                for (int mi = 0; mi < 4; mi++) {
                    mma16816(cfr[mi][2 * np],     ah[mi], bh);       // hi*hi
                    mma16816(cfr[mi][2 * np],     ah[mi], bl);       // hi*lo
                    mma16816(cfr[mi][2 * np],     al[mi], bh);       // lo*hi
                    mma16816(cfr[mi][2 * np + 1], ah[mi], bh + 2);
                    mma16816(cfr[mi][2 * np + 1], ah[mi], bl + 2);
                    mma16816(cfr[mi][2 * np + 1], al[mi], bh + 2);
                }
            }
        }
        __syncthreads();    // protect stage about to be overwritten by next prefetch
    }

    // ---- epilogue ----
    #pragma unroll
    for (int mi = 0; mi < 4; mi++) {
        #pragma unroll
        for (int h = 0; h < 2; h++) {
            const size_t b = (size_t)(b0 + mi * 16 + gid + 8 * h);
            #pragma unroll
            for (int ni = 0; ni < 8; ni++) {
                const int n = nb + ni * 8 + 2 * tig;
                float a0 = cfr[mi][ni][2 * h];
                float a1 = cfr[mi][ni][2 * h + 1];
                if (EPI == 0) {
                    float v0a = a0 + __ldg(bias + n);
                    float v0b = a1 + __ldg(bias + n + 1);
                    st2(Oh, Ol, b * 512 + n, 2.0f * tanhf(v0a), 2.0f * tanhf(v0b));
                    st2(Oh, Ol, b * 512 + 256 + n,
                        v0a + 0.1f * __ldg(qn + n), v0b + 0.1f * __ldg(qn + n + 1));
                } else if (EPI == 1) {
                    st2(Oh, Ol, b * 256 + n, a0, a1);
                } else {
                    float r0a, r0b;
                    ld2(auxh, auxl, b * 512 + 256 + n, r0a, r0b);
                    float v0a = r0a - a0, v0b = r0b - a1;
                    if (EPI == 2) {
                        float v1a, v1b;
                        ld2(Ah, Al, b * 256 + n, v1a, v1b);     // A operand IS v1
                        st2(Oh, Ol, b * 512 + n, v1a + tanhf(v0a), v1b + tanhf(v0b));
                        st2(Oh, Ol, b * 512 + 256 + n,
                            v0a + 0.1f * __ldg(qn + n), v0b + 0.1f * __ldg(qn + n + 1));
                    } else {
                        st2(Oh, Ol, b * 256 + n, v0a, v0b);
                    }
                }
            }
        }
    }
}

// ======================= split kernels =======================
__global__ void xsplit(const float* __restrict__ x,
                       __nv_bfloat16* __restrict__ xh, __nv_bfloat16* __restrict__ xl) {
    size_t bb = blockIdx.x;
    for (int d = threadIdx.x; d < KX; d += 256) {
        float v = (d < INDIM) ? x[bb * INDIM + d] : 0.0f;
        __nv_bfloat16 h = __float2bfloat16(v);
        xh[bb * KX + d] = h;
        xl[bb * KX + d] = __float2bfloat16(v - __bfloat162float(h));
    }
}

__global__ void wtsplit(const float* __restrict__ Win,
                        __nv_bfloat16* __restrict__ wh, __nv_bfloat16* __restrict__ wl) {
    int i = blockIdx.x;   // output unit
    for (int d = threadIdx.x; d < KX; d += 256) {
        float v = (d < INDIM) ? Win[(size_t)d * U + i] : 0.0f;
        __nv_bfloat16 h = __float2bfloat16(v);
        wh[(size_t)i * KX + d] = h;
        wl[(size_t)i * KX + d] = __float2bfloat16(v - __bfloat162float(h));
    }
}

__global__ void splitArr(const float* __restrict__ s,
                         __nv_bfloat16* __restrict__ h, __nv_bfloat16* __restrict__ l, int n) {
    int i = blockIdx.x * 256 + threadIdx.x;
    if (i < n) {
        float v = s[i];
        __nv_bfloat16 hh = __float2bfloat16(v);
        h[i] = hh;
        l[i] = __float2bfloat16(v - __bfloat162float(hh));
    }
}

// ======================= fp32 precompute path (Newton-Schulz) =======================
template <int TA, int TB>
__global__ void gemm256(const float* __restrict__ Aall, const float* __restrict__ Ball,
                        float* __restrict__ Call, int ldc, int cofs,
                        float alpha, float dval)
{
    const float* A  = Aall + (size_t)blockIdx.z * (U * U);
    const float* Bm = Ball + (size_t)blockIdx.z * (U * U);
    float*       C  = Call + (size_t)blockIdx.z * (U * ldc);

    __shared__ float As[16][68];
    __shared__ float Bs[16][68];

    int t = threadIdx.x, tx = t & 15, ty = t >> 4;
    int i0 = blockIdx.y * 64, j0 = blockIdx.x * 64;
    float acc[4][4] = {};

    for (int k0 = 0; k0 < U; k0 += 16) {
        if (TA == 0) {
            int i = t >> 2, k4 = (t & 3) * 4;
            float4 v = *(const float4*)&A[(i0 + i) * U + k0 + k4];
            As[k4 + 0][i] = v.x; As[k4 + 1][i] = v.y; As[k4 + 2][i] = v.z; As[k4 + 3][i] = v.w;
        } else {
            int k = t >> 4, i4 = (t & 15) * 4;
            float4 v = *(const float4*)&A[(k0 + k) * U + i0 + i4];
            As[k][i4 + 0] = v.x; As[k][i4 + 1] = v.y; As[k][i4 + 2] = v.z; As[k][i4 + 3] = v.w;
        }
        if (TB == 0) {
            int k = t >> 4, j4 = (t & 15) * 4;
            float4 v = *(const float4*)&Bm[(k0 + k) * U + j0 + j4];
            Bs[k][j4 + 0] = v.x; Bs[k][j4 + 1] = v.y; Bs[k][j4 + 2] = v.z; Bs[k][j4 + 3] = v.w;
        } else {
            int j = t >> 2, k4 = (t & 3) * 4;
            float4 v = *(const float4*)&Bm[(j0 + j) * U + k0 + k4];
            Bs[k4 + 0][j] = v.x; Bs[k4 + 1][j] = v.y; Bs[k4 + 2][j] = v.z; Bs[k4 + 3][j] = v.w;
        }
        __syncthreads();
        #pragma unroll
        for (int k = 0; k < 16; k++) {
            float a[4], b[4];
            #pragma unroll
            for (int rr = 0; rr < 4; rr++) a[rr] = As[k][ty * 4 + rr];
            #pragma unroll
            for (int cci = 0; cci < 4; cci++) b[cci] = Bs[k][tx * 4 + cci];
            #pragma unroll
            for (int rr = 0; rr < 4; rr++)
                #pragma unroll
                for (int cci = 0; cci < 4; cci++)
                    acc[rr][cci] += a[rr] * b[cci];
        }
        __syncthreads();
    }
    #pragma unroll
    for (int rr = 0; rr < 4; rr++) {
        int gi = i0 + ty * 4 + rr;
        #pragma unroll
        for (int cci = 0; cci < 4; cci++) {
            int gj = j0 + tx * 4 + cci;
            C[gi * ldc + cofs + gj] = alpha * acc[rr][cci] + ((gi == gj) ? dval : 0.0f);
        }
    }
}

// X0 = 2/(2+||M||inf) * I, 1024 threads/layer (4-way split of the column sums)
__global__ void initX(const float* __restrict__ Mall, float* __restrict__ Xall) {
    int l = blockIdx.x;
    const float* M = Mall + (size_t)l * U * U;
    float*       X = Xall + (size_t)l * U * U;
    int t = threadIdx.x;
    int j = t & 255, part = t >> 8;          // 4 parts of 64 rows

    float s = 0.0f;
    #pragma unroll 8
    for (int r = part * 64; r < part * 64 + 64; r++) s += fabsf(M[r * U + j]);

    __shared__ float red[1024];
    red[t] = s; __syncthreads();
    if (part == 0) {
        float cs = red[j] + red[j + 256] + red[j + 512] + red[j + 768];
        red[j] = cs;
    }
    __syncthreads();
    for (int o = 128; o > 0; o >>= 1) {
        if (t < o) red[t] = fmaxf(red[t], red[t + o]);
        __syncthreads();
    }
    float c = 2.0f / (2.0f + red[0]);
    for (int e = t; e < U * U; e += 1024)
        X[e] = ((e >> 8) == (e & 255)) ? c : 0.0f;
}

__global__ void copyE(const float* __restrict__ X, float* __restrict__ E) {
    int idx = blockIdx.x * blockDim.x + threadIdx.x;   // NL*U*U
    int l = idx >> 16, rr = (idx >> 8) & 255, cc = idx & 255;
    E[(size_t)l * U * 512 + rr * 512 + cc] = X[idx];
}

// ======================= output projection =======================
__global__ void outKernel(const __nv_bfloat16* __restrict__ v0h,
                          const __nv_bfloat16* __restrict__ v0l,
                          const float* __restrict__ Wout, const float* __restrict__ bout,
                          float* __restrict__ out) {
    __shared__ float Ws[U * ODIM];
    __shared__ float bs[ODIM];
    int t = threadIdx.x;
    for (int j = t; j < U * ODIM; j += 256) Ws[j] = Wout[j];
    if (t < ODIM) bs[t] = bout[t];
    __syncthreads();

    int w = t >> 5, lane = t & 31;
    size_t b = (size_t)blockIdx.x * 8 + w;
    float acc[ODIM] = {};
    for (int n = lane; n < U; n += 32) {
        float v = __bfloat162float(v0h[b * U + n]) + __bfloat162float(v0l[b * U + n]);
        #pragma unroll
        for (int o = 0; o < ODIM; o++) acc[o] += v * Ws[n * ODIM + o];
    }
    #pragma unroll
    for (int o = 0; o < ODIM; o++)
        #pragma unroll
        for (int s = 16; s > 0; s >>= 1) acc[o] += __shfl_xor_sync(0xFFFFFFFFu, acc[o], s);
    if (lane < ODIM) out[b * ODIM + lane] = acc[lane] + bs[lane];
}

// ======================= launch =======================
extern "C" void kernel_launch(void* const* d_in, const int* in_sizes, int n_in,
                              void* d_out, int out_size)
{
    (void)in_sizes; (void)n_in; (void)out_size;
    const float* x     = (const float*)d_in[0];
    const float* W_in  = (const float*)d_in[1];
    const float* b_in  = (const float*)d_in[2];
    const float* B0    = (const float*)d_in[3];
    const float* q     = (const float*)d_in[4];
    const float* W_out = (const float*)d_in[5];
    const float* b_out = (const float*)d_in[6];
    float* out = (float*)d_out;

    unsigned char* pool;
    cudaGetSymbolAddress((void**)&pool, g_pool);
    __nv_bfloat16* xh  = (__nv_bfloat16*)(pool + O_XH);
    __nv_bfloat16* xl  = (__nv_bfloat16*)(pool + O_XL);
    __nv_bfloat16* wth = (__nv_bfloat16*)(pool + O_WTH);
    __nv_bfloat16* wtl = (__nv_bfloat16*)(pool + O_WTL);
    __nv_bfloat16* Rh  = (__nv_bfloat16*)(pool + O_RH);
    __nv_bfloat16* Rl  = (__nv_bfloat16*)(pool + O_RL);
    __nv_bfloat16* v1h = (__nv_bfloat16*)(pool + O_V1H);
    __nv_bfloat16* v1l = (__nv_bfloat16*)(pool + O_V1L);
    __nv_bfloat16* v0h = (__nv_bfloat16*)(pool + O_V0H);
    __nv_bfloat16* v0l = (__nv_bfloat16*)(pool + O_V0L);
    __nv_bfloat16* Eh  = (__nv_bfloat16*)(pool + O_EH);
    __nv_bfloat16* El  = (__nv_bfloat16*)(pool + O_EL);
    __nv_bfloat16* Bh  = (__nv_bfloat16*)(pool + O_BH);
    __nv_bfloat16* Bl  = (__nv_bfloat16*)(pool + O_BL);
    float* pM  = (float*)(pool + O_M);
    float* pXa = (float*)(pool + O_XA);
    float* pXb = (float*)(pool + O_XB);
    float* pT  = (float*)(pool + O_T);
    float* pE  = (float*)(pool + O_EF);

    static int smem_set = 0;
    if (!smem_set) {
        cudaFuncSetAttribute(mmaGemm<0>, cudaFuncAttributeMaxDynamicSharedMemorySize, SMEM_TOT);
        cudaFuncSetAttribute(mmaGemm<1>, cudaFuncAttributeMaxDynamicSharedMemorySize, SMEM_TOT);
        cudaFuncSetAttribute(mmaGemm<2>, cudaFuncAttributeMaxDynamicSharedMemorySize, SMEM_TOT);
        cudaFuncSetAttribute(mmaGemm<3>, cudaFuncAttributeMaxDynamicSharedMemorySize, SMEM_TOT);
        smem_set = 1;
    }

    // ---- operand splits ----
    xsplit<<<BATCHN, 256>>>(x, xh, xl);
    wtsplit<<<U, 256>>>(W_in, wth, wtl);

    // ---- Newton-Schulz inverse precompute (fp32) ----
    dim3 gs(4, 4, NL);
    gemm256<1, 0><<<gs, 256>>>(B0, B0, pM, U, 0, 1.0f, 2.0f);       // M = 2I + B^T B
    initX<<<NL, 1024>>>(pM, pXa);
    float* Xc = pXa; float* Xn = pXb;
    for (int it = 0; it < 7; it++) {
        gemm256<0, 0><<<gs, 256>>>(pM, Xc, pT, U, 0, -1.0f, 2.0f);  // T = 2I - M X
        gemm256<0, 0><<<gs, 256>>>(Xc, pT, Xn, U, 0, 1.0f, 0.0f);   // X <- X T
        float* tmp = Xc; Xc = Xn; Xn = tmp;
    }
    copyE<<<NL * U * U / 256, 256>>>(Xc, pE);                       // E[:, :256] = Minv
    gemm256<0, 1><<<gs, 256>>>(Xc, B0, pE, 2 * U, U, 1.0f, 0.0f);   // E[:, 256:] = Minv B^T
    splitArr<<<(NL * U * 2 * U + 255) / 256, 256>>>(pE, Eh, El, NL * U * 2 * U);
    splitArr<<<(NL * U * U + 255) / 256, 256>>>(B0, Bh, Bl, NL * U * U);

    // ---- input layer: R_0 from x @ W_in + b_in (fused tanh epilogue) ----
    mmaGemm<0><<<BATCHN / 64, 128, SMEM_TOT>>>(xh, xl, KX, wth, wtl,
                                               b_in, q, nullptr, nullptr, Rh, Rl);

    // ---- 8 implicit layers: two HMMA GEMMs each ----
    for (int l = 0; l < NL; l++) {
        // v1 = E_l @ [r1; r0]
        mmaGemm<1><<<BATCHN / 64, 128, SMEM_TOT>>>(Rh, Rl, 2 * U,
                                                   Eh + (size_t)l * U * 2 * U,
                                                   El + (size_t)l * U * 2 * U,
                                                   nullptr, nullptr, nullptr, nullptr,
                                                   v1h, v1l);
        if (l < NL - 1) {
            // v0 = r0 - B_l v1; fused: write next layer's R in place
            mmaGemm<2><<<BATCHN / 64, 128, SMEM_TOT>>>(v1h, v1l, U,
                                                       Bh + (size_t)l * U * U,
                                                       Bl + (size_t)l * U * U,
                                                       nullptr, q + (size_t)(l + 1) * U,
                                                       Rh, Rl, Rh, Rl);
        } else {
            mmaGemm<3><<<BATCHN / 64, 128, SMEM_TOT>>>(v1h, v1l, U,
                                                       Bh + (size_t)l * U * U,
                                                       Bl + (size_t)l * U * U,
                                                       nullptr, nullptr,
                                                       Rh, Rl, v0h, v0l);
        }
    }

    outKernel<<<BATCHN / 8, 256>>>(v0h, v0l, W_out, b_out, out);
}

// round 8
// speedup vs baseline: 1.0208x; 1.0208x over previous
#include <cuda_runtime.h>
#include <cuda_bf16.h>
#include <math.h>
#include <stdint.h>

#define U      256
#define BATCHN 32768
#define NL     8
#define INDIM  784
#define ODIM   10
#define KX     832            // INDIM padded to a multiple of 32

// ======================= device memory pool (no allocations) =======================
static constexpr size_t O_XH  = 0;
static constexpr size_t O_XL  = O_XH  + (size_t)BATCHN * KX * 2;
static constexpr size_t O_WTH = O_XL  + (size_t)BATCHN * KX * 2;
static constexpr size_t O_WTL = O_WTH + (size_t)U * KX * 2;
static constexpr size_t O_RH  = O_WTL + (size_t)U * KX * 2;
static constexpr size_t O_RL  = O_RH  + (size_t)BATCHN * 2 * U * 2;
static constexpr size_t O_V1H = O_RL  + (size_t)BATCHN * 2 * U * 2;
static constexpr size_t O_V1L = O_V1H + (size_t)BATCHN * U * 2;
static constexpr size_t O_V0H = O_V1L + (size_t)BATCHN * U * 2;
static constexpr size_t O_V0L = O_V0H + (size_t)BATCHN * U * 2;
static constexpr size_t O_EH  = O_V0L + (size_t)BATCHN * U * 2;
static constexpr size_t O_EL  = O_EH  + (size_t)NL * U * 2 * U * 2;
static constexpr size_t O_BH  = O_EL  + (size_t)NL * U * 2 * U * 2;
static constexpr size_t O_BL  = O_BH  + (size_t)NL * U * U * 2;
static constexpr size_t O_M   = O_BL  + (size_t)NL * U * U * 2;
static constexpr size_t O_XA  = O_M   + (size_t)NL * U * U * 4;
static constexpr size_t O_XB  = O_XA  + (size_t)NL * U * U * 4;
static constexpr size_t O_T   = O_XB  + (size_t)NL * U * U * 4;
static constexpr size_t O_EF  = O_T   + (size_t)NL * U * U * 4;
static constexpr size_t POOLSZ = O_EF + (size_t)NL * U * 2 * U * 4;

__device__ __align__(1024) unsigned char g_pool[POOLSZ];

// ======================= mma.sync helpers (baseline PTX, legal on compute_103) =======
__device__ __forceinline__ void mma16816(float* c, const uint32_t* a, const uint32_t* b) {
    asm volatile(
        "mma.sync.aligned.m16n8k16.row.col.f32.bf16.bf16.f32 "
        "{%0,%1,%2,%3}, {%4,%5,%6,%7}, {%8,%9}, {%0,%1,%2,%3};"
        : "+f"(c[0]), "+f"(c[1]), "+f"(c[2]), "+f"(c[3])
        : "r"(a[0]), "r"(a[1]), "r"(a[2]), "r"(a[3]), "r"(b[0]), "r"(b[1]));
}

__device__ __forceinline__ void ldsm4(uint32_t* r, uint32_t addr) {
    asm volatile("ldmatrix.sync.aligned.m8n8.x4.shared.b16 {%0,%1,%2,%3}, [%4];"
                 : "=r"(r[0]), "=r"(r[1]), "=r"(r[2]), "=r"(r[3]) : "r"(addr));
}

// 64B rows, 4x 16B granules, XOR swizzle keyed on row bits 1-2 -> conflict-free LDSM/STS
__device__ __forceinline__ uint32_t swb(int row, int g) {
    return (uint32_t)(row * 64 + ((g ^ ((row >> 1) & 3)) * 16));
}

__device__ __forceinline__ void cpasync16(uint32_t daddr, const void* src) {
    asm volatile("cp.async.cg.shared.global [%0], [%1], 16;" :: "r"(daddr), "l"(src));
}

// split / merge helpers for bf16-pair fp32 emulation
__device__ __forceinline__ void st2(__nv_bfloat16* h, __nv_bfloat16* l, size_t idx,
                                    float x0, float x1) {
    __nv_bfloat16 h0 = __float2bfloat16(x0);
    __nv_bfloat16 h1 = __float2bfloat16(x1);
    __nv_bfloat162 hv; hv.x = h0; hv.y = h1;
    __nv_bfloat162 lv;
    lv.x = __float2bfloat16(x0 - __bfloat162float(h0));
    lv.y = __float2bfloat16(x1 - __bfloat162float(h1));
    *(__nv_bfloat162*)(h + idx) = hv;
    *(__nv_bfloat162*)(l + idx) = lv;
}

__device__ __forceinline__ void ld2(const __nv_bfloat16* h, const __nv_bfloat16* l, size_t idx,
                                    float& x0, float& x1) {
    __nv_bfloat162 hv = *(const __nv_bfloat162*)(h + idx);
    __nv_bfloat162 lv = *(const __nv_bfloat162*)(l + idx);
    x0 = __bfloat162float(hv.x) + __bfloat162float(lv.x);
    x1 = __bfloat162float(hv.y) + __bfloat162float(lv.y);
}

// ======================= HMMA bf16-split GEMM =======================
// D[b0..b0+63][0..255] = sum_k A[b][k] * B[n][k]; A/B bf16 hi/lo pairs, fp32 accum,
// 3 products (hh + hl + lh) issued in SEPARATE ROUNDS so no back-to-back accumulator RAW.
// 8 warps (256 thr): all warps share the 64 M-rows; warp w owns N in [32w, 32w+32).
// EPI 0: input layer  -> layer-0 R:  r1 = 2*tanh(acc+bias), r0 = acc+bias+0.1*q
// EPI 1: z1 GEMM      -> v1 pair
// EPI 2: z0 GEMM l<7  -> v0 = r0_aux - acc; next R: r1 = v1 + tanh(v0), r0 = v0 + 0.1*q
// EPI 3: z0 GEMM l=7  -> v0 = r0_aux - acc -> v0 pair
#define A_SZ     4096        // 64 rows x 64B
#define B_SZ     16384       // 256 rows x 64B
#define STAGE_SZ (2 * A_SZ + 2 * B_SZ)           // 40 KB
#define SMEM_TOT (2 * STAGE_SZ)                  // 80 KB (double buffer)

__device__ __forceinline__ void load_chunk(
    uint32_t sbase, const __nv_bfloat16* __restrict__ Ah, const __nv_bfloat16* __restrict__ Al,
    const __nv_bfloat16* __restrict__ Bh, const __nv_bfloat16* __restrict__ Bl,
    int lda, int b0, int k0, int tid)
{
    #pragma unroll
    for (int i = tid; i < 2560; i += 256) {
        const __nv_bfloat16* src; uint32_t dst;
        if (i < 512) {
            int part = i >> 8, idx = i & 255, row = idx >> 2, g = idx & 3;
            src = (part ? Al : Ah) + (size_t)(b0 + row) * lda + k0 + g * 8;
            dst = sbase + part * A_SZ + swb(row, g);
        } else {
            int j = i - 512;
            int part = j >> 10, idx = j & 1023, row = idx >> 2, g = idx & 3;
            src = (part ? Bl : Bh) + (size_t)row * lda + k0 + g * 8;
            dst = sbase + 2 * A_SZ + part * B_SZ + swb(row, g);
        }
        cpasync16(dst, src);
    }
    asm volatile("cp.async.commit_group;" ::: "memory");
}

template <int EPI>
__global__ void __launch_bounds__(256, 2)
mmaGemm(const __nv_bfloat16* __restrict__ Ah, const __nv_bfloat16* __restrict__ Al, int lda,
        const __nv_bfloat16* __restrict__ Bh, const __nv_bfloat16* __restrict__ Bl,
        const float* __restrict__ bias, const float* __restrict__ qn,
        const __nv_bfloat16* __restrict__ auxh, const __nv_bfloat16* __restrict__ auxl,
        __nv_bfloat16* __restrict__ Oh, __nv_bfloat16* __restrict__ Ol)
{
    extern __shared__ __align__(128) unsigned char smem[];
    const uint32_t sb = (uint32_t)__cvta_generic_to_shared(smem);

    const int tid  = threadIdx.x;
    const int warp = tid >> 5, lane = tid & 31;
    const int gid  = lane >> 2, tig = lane & 3;
    const int b0   = blockIdx.x * 64;
    const int nb   = warp * 32;                 // warp's N base (8 warps x 32)

    float cfr[4][4][4] = {};                    // [mi][ni][reg], 64 regs

    const int nchunk = lda >> 5;

    // prologue: prefetch chunk 0 into stage 0
    load_chunk(sb, Ah, Al, Bh, Bl, lda, b0, 0, tid);

    for (int ch = 0; ch < nchunk; ch++) {
        if (ch + 1 < nchunk) {
            load_chunk(sb + ((ch + 1) & 1) * STAGE_SZ, Ah, Al, Bh, Bl,
                       lda, b0, (ch + 1) << 5, tid);
            asm volatile("cp.async.wait_group 1;" ::: "memory");
        } else {
            asm volatile("cp.async.wait_group 0;" ::: "memory");
        }
        __syncthreads();

        const uint32_t st  = sb + (ch & 1) * STAGE_SZ;
        const uint32_t sAh = st, sAl = st + A_SZ;
        const uint32_t sBh = st + 2 * A_SZ, sBl = st + 2 * A_SZ + B_SZ;

        #pragma unroll
        for (int ks = 0; ks < 2; ks++) {
            uint32_t ah[4][4], al[4][4], bh[2][4], bl[2][4];
            const int arow = (lane & 15);
            const int agr  = ks * 2 + (lane >> 4);
            #pragma unroll
            for (int mi = 0; mi < 4; mi++) {
                uint32_t off = swb(mi * 16 + arow, agr);
                ldsm4(ah[mi], sAh + off);
                ldsm4(al[mi], sAl + off);
            }
            const int brow = (lane & 7) + ((lane >> 4) << 3);
            const int bgr  = ks * 2 + ((lane >> 3) & 1);
            #pragma unroll
            for (int nj = 0; nj < 2; nj++) {
                uint32_t off = swb(nb + nj * 16 + brow, bgr);
                ldsm4(bh[nj], sBh + off);
                ldsm4(bl[nj], sBl + off);
            }
            // round 1: hi*hi — 16 independent MMAs
            #pragma unroll
            for (int mi = 0; mi < 4; mi++)
                #pragma unroll
                for (int nj = 0; nj < 2; nj++) {
                    mma16816(cfr[mi][2 * nj],     ah[mi], bh[nj]);
                    mma16816(cfr[mi][2 * nj + 1], ah[mi], bh[nj] + 2);
                }
            // round 2: hi*lo — same accumulators, 16 MMAs apart
            #pragma unroll
            for (int mi = 0; mi < 4; mi++)
                #pragma unroll
                for (int nj = 0; nj < 2; nj++) {
                    mma16816(cfr[mi][2 * nj],     ah[mi], bl[nj]);
                    mma16816(cfr[mi][2 * nj + 1], ah[mi], bl[nj] + 2);
                }
            // round 3: lo*hi
            #pragma unroll
            for (int mi = 0; mi < 4; mi++)
                #pragma unroll
                for (int nj = 0; nj < 2; nj++) {
                    mma16816(cfr[mi][2 * nj],     al[mi], bh[nj]);
                    mma16816(cfr[mi][2 * nj + 1], al[mi], bh[nj] + 2);
                }
        }
        __syncthreads();    // protect stage about to be overwritten by next prefetch
    }

    // ---- epilogue ----
    #pragma unroll
    for (int mi = 0; mi < 4; mi++) {
        #pragma unroll
        for (int h = 0; h < 2; h++) {
            const size_t b = (size_t)(b0 + mi * 16 + gid + 8 * h);
            #pragma unroll
            for (int ni = 0; ni < 4; ni++) {
                const int n = nb + ni * 8 + 2 * tig;
                float a0 = cfr[mi][ni][2 * h];
                float a1 = cfr[mi][ni][2 * h + 1];
                if (EPI == 0) {
                    float v0a = a0 + __ldg(bias + n);
                    float v0b = a1 + __ldg(bias + n + 1);
                    st2(Oh, Ol, b * 512 + n, 2.0f * tanhf(v0a), 2.0f * tanhf(v0b));
                    st2(Oh, Ol, b * 512 + 256 + n,
                        v0a + 0.1f * __ldg(qn + n), v0b + 0.1f * __ldg(qn + n + 1));
                } else if (EPI == 1) {
                    st2(Oh, Ol, b * 256 + n, a0, a1);
                } else {
                    float r0a, r0b;
                    ld2(auxh, auxl, b * 512 + 256 + n, r0a, r0b);
                    float v0a = r0a - a0, v0b = r0b - a1;
                    if (EPI == 2) {
                        float v1a, v1b;
                        ld2(Ah, Al, b * 256 + n, v1a, v1b);     // A operand IS v1
                        st2(Oh, Ol, b * 512 + n, v1a + tanhf(v0a), v1b + tanhf(v0b));
                        st2(Oh, Ol, b * 512 + 256 + n,
                            v0a + 0.1f * __ldg(qn + n), v0b + 0.1f * __ldg(qn + n + 1));
                    } else {
                        st2(Oh, Ol, b * 256 + n, v0a, v0b);
                    }
                }
            }
        }
    }
}

// ======================= split kernels =======================
__global__ void xsplit(const float* __restrict__ x,
                       __nv_bfloat16* __restrict__ xh, __nv_bfloat16* __restrict__ xl) {
    size_t bb = blockIdx.x;
    for (int d = threadIdx.x; d < KX; d += 256) {
        float v = (d < INDIM) ? x[bb * INDIM + d] : 0.0f;
        __nv_bfloat16 h = __float2bfloat16(v);
        xh[bb * KX + d] = h;
        xl[bb * KX + d] = __float2bfloat16(v - __bfloat162float(h));
    }
}

__global__ void wtsplit(const float* __restrict__ Win,
                        __nv_bfloat16* __restrict__ wh, __nv_bfloat16* __restrict__ wl) {
    int i = blockIdx.x;   // output unit
    for (int d = threadIdx.x; d < KX; d += 256) {
        float v = (d < INDIM) ? Win[(size_t)d * U + i] : 0.0f;
        __nv_bfloat16 h = __float2bfloat16(v);
        wh[(size_t)i * KX + d] = h;
        wl[(size_t)i * KX + d] = __float2bfloat16(v - __bfloat162float(h));
    }
}

__global__ void splitArr(const float* __restrict__ s,
                         __nv_bfloat16* __restrict__ h, __nv_bfloat16* __restrict__ l, int n) {
    int i = blockIdx.x * 256 + threadIdx.x;
    if (i < n) {
        float v = s[i];
        __nv_bfloat16 hh = __float2bfloat16(v);
        h[i] = hh;
        l[i] = __float2bfloat16(v - __bfloat162float(hh));
    }
}

// ======================= fp32 precompute path (Newton-Schulz) =======================
template <int TA, int TB>
__global__ void gemm256(const float* __restrict__ Aall, const float* __restrict__ Ball,
                        float* __restrict__ Call, int ldc, int cofs,
                        float alpha, float dval)
{
    const float* A  = Aall + (size_t)blockIdx.z * (U * U);
    const float* Bm = Ball + (size_t)blockIdx.z * (U * U);
    float*       C  = Call + (size_t)blockIdx.z * (U * ldc);

    __shared__ float As[16][68];
    __shared__ float Bs[16][68];

    int t = threadIdx.x, tx = t & 15, ty = t >> 4;
    int i0 = blockIdx.y * 64, j0 = blockIdx.x * 64;
    float acc[4][4] = {};

    for (int k0 = 0; k0 < U; k0 += 16) {
        if (TA == 0) {
            int i = t >> 2, k4 = (t & 3) * 4;
            float4 v = *(const float4*)&A[(i0 + i) * U + k0 + k4];
            As[k4 + 0][i] = v.x; As[k4 + 1][i] = v.y; As[k4 + 2][i] = v.z; As[k4 + 3][i] = v.w;
        } else {
            int k = t >> 4, i4 = (t & 15) * 4;
            float4 v = *(const float4*)&A[(k0 + k) * U + i0 + i4];
            As[k][i4 + 0] = v.x; As[k][i4 + 1] = v.y; As[k][i4 + 2] = v.z; As[k][i4 + 3] = v.w;
        }
        if (TB == 0) {
            int k = t >> 4, j4 = (t & 15) * 4;
            float4 v = *(const float4*)&Bm[(k0 + k) * U + j0 + j4];
            Bs[k][j4 + 0] = v.x; Bs[k][j4 + 1] = v.y; Bs[k][j4 + 2] = v.z; Bs[k][j4 + 3] = v.w;
        } else {
            int j = t >> 2, k4 = (t & 3) * 4;
            float4 v = *(const float4*)&Bm[(j0 + j) * U + k0 + k4];
            Bs[k4 + 0][j] = v.x; Bs[k4 + 1][j] = v.y; Bs[k4 + 2][j] = v.z; Bs[k4 + 3][j] = v.w;
        }
        __syncthreads();
        #pragma unroll
        for (int k = 0; k < 16; k++) {
            float a[4], b[4];
            #pragma unroll
            for (int rr = 0; rr < 4; rr++) a[rr] = As[k][ty * 4 + rr];
            #pragma unroll
            for (int cci = 0; cci < 4; cci++) b[cci] = Bs[k][tx * 4 + cci];
            #pragma unroll
            for (int rr = 0; rr < 4; rr++)
                #pragma unroll
                for (int cci = 0; cci < 4; cci++)
                    acc[rr][cci] += a[rr] * b[cci];
        }
        __syncthreads();
    }
    #pragma unroll
    for (int rr = 0; rr < 4; rr++) {
        int gi = i0 + ty * 4 + rr;
        #pragma unroll
        for (int cci = 0; cci < 4; cci++) {
            int gj = j0 + tx * 4 + cci;
            C[gi * ldc + cofs + gj] = alpha * acc[rr][cci] + ((gi == gj) ? dval : 0.0f);
        }
    }
}

// X0 = 2/(2+||M||inf) * I, 1024 threads/layer (4-way split of the column sums)
__global__ void initX(const float* __restrict__ Mall, float* __restrict__ Xall) {
    int l = blockIdx.x;
    const float* M = Mall + (size_t)l * U * U;
    float*       X = Xall + (size_t)l * U * U;
    int t = threadIdx.x;
    int j = t & 255, part = t >> 8;          // 4 parts of 64 rows

    float s = 0.0f;
    #pragma unroll 8
    for (int r = part * 64; r < part * 64 + 64; r++) s += fabsf(M[r * U + j]);

    __shared__ float red[1024];
    red[t] = s; __syncthreads();
    if (part == 0) {
        float cs = red[j] + red[j + 256] + red[j + 512] + red[j + 768];
        red[j] = cs;
    }
    __syncthreads();
    for (int o = 128; o > 0; o >>= 1) {
        if (t < o) red[t] = fmaxf(red[t], red[t + o]);
        __syncthreads();
    }
    float c = 2.0f / (2.0f + red[0]);
    for (int e = t; e < U * U; e += 1024)
        X[e] = ((e >> 8) == (e & 255)) ? c : 0.0f;
}

__global__ void copyE(const float* __restrict__ X, float* __restrict__ E) {
    int idx = blockIdx.x * blockDim.x + threadIdx.x;   // NL*U*U
    int l = idx >> 16, rr = (idx >> 8) & 255, cc = idx & 255;
    E[(size_t)l * U * 512 + rr * 512 + cc] = X[idx];
}

// ======================= output projection =======================
__global__ void outKernel(const __nv_bfloat16* __restrict__ v0h,
                          const __nv_bfloat16* __restrict__ v0l,
                          const float* __restrict__ Wout, const float* __restrict__ bout,
                          float* __restrict__ out) {
    __shared__ float Ws[U * ODIM];
    __shared__ float bs[ODIM];
    int t = threadIdx.x;
    for (int j = t; j < U * ODIM; j += 256) Ws[j] = Wout[j];
    if (t < ODIM) bs[t] = bout[t];
    __syncthreads();

    int w = t >> 5, lane = t & 31;
    size_t b = (size_t)blockIdx.x * 8 + w;
    float acc[ODIM] = {};
    for (int n = lane; n < U; n += 32) {
        float v = __bfloat162float(v0h[b * U + n]) + __bfloat162float(v0l[b * U + n]);
        #pragma unroll
        for (int o = 0; o < ODIM; o++) acc[o] += v * Ws[n * ODIM + o];
    }
    #pragma unroll
    for (int o = 0; o < ODIM; o++)
        #pragma unroll
        for (int s = 16; s > 0; s >>= 1) acc[o] += __shfl_xor_sync(0xFFFFFFFFu, acc[o], s);
    if (lane < ODIM) out[b * ODIM + lane] = acc[lane] + bs[lane];
}

// ======================= launch =======================
extern "C" void kernel_launch(void* const* d_in, const int* in_sizes, int n_in,
                              void* d_out, int out_size)
{
    (void)in_sizes; (void)n_in; (void)out_size;
    const float* x     = (const float*)d_in[0];
    const float* W_in  = (const float*)d_in[1];
    const float* b_in  = (const float*)d_in[2];
    const float* B0    = (const float*)d_in[3];
    const float* q     = (const float*)d_in[4];
    const float* W_out = (const float*)d_in[5];
    const float* b_out = (const float*)d_in[6];
    float* out = (float*)d_out;

    unsigned char* pool;
    cudaGetSymbolAddress((void**)&pool, g_pool);
    __nv_bfloat16* xh  = (__nv_bfloat16*)(pool + O_XH);
    __nv_bfloat16* xl  = (__nv_bfloat16*)(pool + O_XL);
    __nv_bfloat16* wth = (__nv_bfloat16*)(pool + O_WTH);
    __nv_bfloat16* wtl = (__nv_bfloat16*)(pool + O_WTL);
    __nv_bfloat16* Rh  = (__nv_bfloat16*)(pool + O_RH);
    __nv_bfloat16* Rl  = (__nv_bfloat16*)(pool + O_RL);
    __nv_bfloat16* v1h = (__nv_bfloat16*)(pool + O_V1H);
    __nv_bfloat16* v1l = (__nv_bfloat16*)(pool + O_V1L);
    __nv_bfloat16* v0h = (__nv_bfloat16*)(pool + O_V0H);
    __nv_bfloat16* v0l = (__nv_bfloat16*)(pool + O_V0L);
    __nv_bfloat16* Eh  = (__nv_bfloat16*)(pool + O_EH);
    __nv_bfloat16* El  = (__nv_bfloat16*)(pool + O_EL);
    __nv_bfloat16* Bh  = (__nv_bfloat16*)(pool + O_BH);
    __nv_bfloat16* Bl  = (__nv_bfloat16*)(pool + O_BL);
    float* pM  = (float*)(pool + O_M);
    float* pXa = (float*)(pool + O_XA);
    float* pXb = (float*)(pool + O_XB);
    float* pT  = (float*)(pool + O_T);
    float* pE  = (float*)(pool + O_EF);

    static int smem_set = 0;
    if (!smem_set) {
        cudaFuncSetAttribute(mmaGemm<0>, cudaFuncAttributeMaxDynamicSharedMemorySize, SMEM_TOT);
        cudaFuncSetAttribute(mmaGemm<1>, cudaFuncAttributeMaxDynamicSharedMemorySize, SMEM_TOT);
        cudaFuncSetAttribute(mmaGemm<2>, cudaFuncAttributeMaxDynamicSharedMemorySize, SMEM_TOT);
        cudaFuncSetAttribute(mmaGemm<3>, cudaFuncAttributeMaxDynamicSharedMemorySize, SMEM_TOT);
        smem_set = 1;
    }

    // ---- operand splits ----
    xsplit<<<BATCHN, 256>>>(x, xh, xl);
    wtsplit<<<U, 256>>>(W_in, wth, wtl);

    // ---- Newton-Schulz inverse precompute (fp32) ----
    dim3 gs(4, 4, NL);
    gemm256<1, 0><<<gs, 256>>>(B0, B0, pM, U, 0, 1.0f, 2.0f);       // M = 2I + B^T B
    initX<<<NL, 1024>>>(pM, pXa);
    float* Xc = pXa; float* Xn = pXb;
    for (int it = 0; it < 6; it++) {
        gemm256<0, 0><<<gs, 256>>>(pM, Xc, pT, U, 0, -1.0f, 2.0f);  // T = 2I - M X
        gemm256<0, 0><<<gs, 256>>>(Xc, pT, Xn, U, 0, 1.0f, 0.0f);   // X <- X T
        float* tmp = Xc; Xc = Xn; Xn = tmp;
    }
    copyE<<<NL * U * U / 256, 256>>>(Xc, pE);                       // E[:, :256] = Minv
    gemm256<0, 1><<<gs, 256>>>(Xc, B0, pE, 2 * U, U, 1.0f, 0.0f);   // E[:, 256:] = Minv B^T
    splitArr<<<(NL * U * 2 * U + 255) / 256, 256>>>(pE, Eh, El, NL * U * 2 * U);
    splitArr<<<(NL * U * U + 255) / 256, 256>>>(B0, Bh, Bl, NL * U * U);

    // ---- input layer: R_0 from x @ W_in + b_in (fused tanh epilogue) ----
    mmaGemm<0><<<BATCHN / 64, 256, SMEM_TOT>>>(xh, xl, KX, wth, wtl,
                                               b_in, q, nullptr, nullptr, Rh, Rl);

    // ---- 8 implicit layers: two HMMA GEMMs each ----
    for (int l = 0; l < NL; l++) {
        // v1 = E_l @ [r1; r0]
        mmaGemm<1><<<BATCHN / 64, 256, SMEM_TOT>>>(Rh, Rl, 2 * U,
                                                   Eh + (size_t)l * U * 2 * U,
                                                   El + (size_t)l * U * 2 * U,
                                                   nullptr, nullptr, nullptr, nullptr,
                                                   v1h, v1l);
        if (l < NL - 1) {
            // v0 = r0 - B_l v1; fused: write next layer's R in place
            mmaGemm<2><<<BATCHN / 64, 256, SMEM_TOT>>>(v1h, v1l, U,
                                                       Bh + (size_t)l * U * U,
                                                       Bl + (size_t)l * U * U,
                                                       nullptr, q + (size_t)(l + 1) * U,
                                                       Rh, Rl, Rh, Rl);
        } else {
            mmaGemm<3><<<BATCHN / 64, 256, SMEM_TOT>>>(v1h, v1l, U,
                                                       Bh + (size_t)l * U * U,
                                                       Bl + (size_t)l * U * U,
                                                       nullptr, nullptr,
                                                       Rh, Rl, v0h, v0l);
        }
    }

    outKernel<<<BATCHN / 8, 256>>>(v0h, v0l, W_out, b_out, out);
}

// round 9
// speedup vs baseline: 1.4450x; 1.4155x over previous
#include <cuda_runtime.h>
#include <cuda_bf16.h>
#include <math.h>
#include <stdint.h>

#define U      256
#define BATCHN 32768
#define NL     8
#define INDIM  784
#define ODIM   10
#define KX     832            // INDIM padded to a multiple of 32

// ======================= device memory pool (no allocations) =======================
static constexpr size_t O_XH  = 0;
static constexpr size_t O_XL  = O_XH  + (size_t)BATCHN * KX * 2;
static constexpr size_t O_WTH = O_XL  + (size_t)BATCHN * KX * 2;
static constexpr size_t O_WTL = O_WTH + (size_t)U * KX * 2;
static constexpr size_t O_RH  = O_WTL + (size_t)U * KX * 2;
static constexpr size_t O_RL  = O_RH  + (size_t)BATCHN * 2 * U * 2;
static constexpr size_t O_V0H = O_RL  + (size_t)BATCHN * 2 * U * 2;
static constexpr size_t O_V0L = O_V0H + (size_t)BATCHN * U * 2;
static constexpr size_t O_EH  = O_V0L + (size_t)BATCHN * U * 2;
static constexpr size_t O_EL  = O_EH  + (size_t)NL * U * 2 * U * 2;
static constexpr size_t O_BH  = O_EL  + (size_t)NL * U * 2 * U * 2;
static constexpr size_t O_BL  = O_BH  + (size_t)NL * U * U * 2;
static constexpr size_t O_M   = O_BL  + (size_t)NL * U * U * 2;
static constexpr size_t O_XA  = O_M   + (size_t)NL * U * U * 4;
static constexpr size_t O_XB  = O_XA  + (size_t)NL * U * U * 4;
static constexpr size_t O_T   = O_XB  + (size_t)NL * U * U * 4;
static constexpr size_t O_EF  = O_T   + (size_t)NL * U * U * 4;
static constexpr size_t POOLSZ = O_EF + (size_t)NL * U * 2 * U * 4;

__device__ __align__(1024) unsigned char g_pool[POOLSZ];

// ======================= mma.sync helpers (baseline PTX, legal on compute_103) =======
__device__ __forceinline__ void mma16816(float* c, const uint32_t* a, const uint32_t* b) {
    asm volatile(
        "mma.sync.aligned.m16n8k16.row.col.f32.bf16.bf16.f32 "
        "{%0,%1,%2,%3}, {%4,%5,%6,%7}, {%8,%9}, {%0,%1,%2,%3};"
        : "+f"(c[0]), "+f"(c[1]), "+f"(c[2]), "+f"(c[3])
        : "r"(a[0]), "r"(a[1]), "r"(a[2]), "r"(a[3]), "r"(b[0]), "r"(b[1]));
}

__device__ __forceinline__ void ldsm4(uint32_t* r, uint32_t addr) {
    asm volatile("ldmatrix.sync.aligned.m8n8.x4.shared.b16 {%0,%1,%2,%3}, [%4];"
                 : "=r"(r[0]), "=r"(r[1]), "=r"(r[2]), "=r"(r[3]) : "r"(addr));
}

// 64B rows, 4x 16B granules, XOR swizzle keyed on row bits 1-2 -> conflict-free LDSM/STS
__device__ __forceinline__ uint32_t swb(int row, int g) {
    return (uint32_t)(row * 64 + ((g ^ ((row >> 1) & 3)) * 16));
}

// split / merge helpers for bf16-pair fp32 emulation
__device__ __forceinline__ void st2(__nv_bfloat16* h, __nv_bfloat16* l, size_t idx,
                                    float x0, float x1) {
    __nv_bfloat16 h0 = __float2bfloat16(x0);
    __nv_bfloat16 h1 = __float2bfloat16(x1);
    __nv_bfloat162 hv; hv.x = h0; hv.y = h1;
    __nv_bfloat162 lv;
    lv.x = __float2bfloat16(x0 - __bfloat162float(h0));
    lv.y = __float2bfloat16(x1 - __bfloat162float(h1));
    *(__nv_bfloat162*)(h + idx) = hv;
    *(__nv_bfloat162*)(l + idx) = lv;
}

__device__ __forceinline__ void ld2(const __nv_bfloat16* h, const __nv_bfloat16* l, size_t idx,
                                    float& x0, float& x1) {
    __nv_bfloat162 hv = *(const __nv_bfloat162*)(h + idx);
    __nv_bfloat162 lv = *(const __nv_bfloat162*)(l + idx);
    x0 = __bfloat162float(hv.x) + __bfloat162float(lv.x);
    x1 = __bfloat162float(hv.y) + __bfloat162float(lv.y);
}

__device__ __forceinline__ uint32_t packbf(float x0, float x1) {
    __nv_bfloat162 v; v.x = __float2bfloat16(x0); v.y = __float2bfloat16(x1);
    return *(uint32_t*)&v;
}

// ======================= input-layer GEMM (K=832): R_0 = f(x @ W_in + b) ============
#define A_SZ     4096        // 64 rows x 64B
#define B_SZ     16384       // 256 rows x 64B
#define IN_SMEM  (2 * A_SZ + 2 * B_SZ)           // 40 KB single buffer

__global__ void __launch_bounds__(256, 2)
inGemm(const __nv_bfloat16* __restrict__ Ah, const __nv_bfloat16* __restrict__ Al,
       const __nv_bfloat16* __restrict__ Bh, const __nv_bfloat16* __restrict__ Bl,
       const float* __restrict__ bias, const float* __restrict__ qn,
       __nv_bfloat16* __restrict__ Oh, __nv_bfloat16* __restrict__ Ol)
{
    __shared__ __align__(128) unsigned char smem[IN_SMEM];
    const uint32_t sb = (uint32_t)__cvta_generic_to_shared(smem);
    const int lda = KX;

    const int tid  = threadIdx.x;
    const int warp = tid >> 5, lane = tid & 31;
    const int gid  = lane >> 2, tig = lane & 3;
    const int b0   = blockIdx.x * 64;
    const int nb   = warp * 32;

    float cfr[4][4][4] = {};

    for (int ch = 0; ch < (KX >> 5); ch++) {
        const int k0 = ch << 5;
        for (int i = tid; i < 2560; i += 256) {
            const __nv_bfloat16* src; unsigned char* dst;
            if (i < 512) {
                int part = i >> 8, idx = i & 255, row = idx >> 2, g = idx & 3;
                src = (part ? Al : Ah) + (size_t)(b0 + row) * lda + k0 + g * 8;
                dst = smem + part * A_SZ + swb(row, g);
            } else {
                int j = i - 512;
                int part = j >> 10, idx = j & 1023, row = idx >> 2, g = idx & 3;
                src = (part ? Bl : Bh) + (size_t)row * lda + k0 + g * 8;
                dst = smem + 2 * A_SZ + part * B_SZ + swb(row, g);
            }
            *(uint4*)dst = *(const uint4*)src;
        }
        __syncthreads();

        const uint32_t sAh = sb, sAl = sb + A_SZ;
        const uint32_t sBh = sb + 2 * A_SZ, sBl = sb + 2 * A_SZ + B_SZ;
        #pragma unroll
        for (int ks = 0; ks < 2; ks++) {
            uint32_t ah[4][4], al[4][4], bh[2][4], bl[2][4];
            const int arow = (lane & 15), agr = ks * 2 + (lane >> 4);
            #pragma unroll
            for (int mi = 0; mi < 4; mi++) {
                uint32_t off = swb(mi * 16 + arow, agr);
                ldsm4(ah[mi], sAh + off); ldsm4(al[mi], sAl + off);
            }
            const int brow = (lane & 7) + ((lane >> 4) << 3);
            const int bgr  = ks * 2 + ((lane >> 3) & 1);
            #pragma unroll
            for (int nj = 0; nj < 2; nj++) {
                uint32_t off = swb(nb + nj * 16 + brow, bgr);
                ldsm4(bh[nj], sBh + off); ldsm4(bl[nj], sBl + off);
            }
            #pragma unroll
            for (int mi = 0; mi < 4; mi++)
                #pragma unroll
                for (int nj = 0; nj < 2; nj++) {
                    mma16816(cfr[mi][2 * nj],     ah[mi], bh[nj]);
                    mma16816(cfr[mi][2 * nj + 1], ah[mi], bh[nj] + 2);
                }
            #pragma unroll
            for (int mi = 0; mi < 4; mi++)
                #pragma unroll
                for (int nj = 0; nj < 2; nj++) {
                    mma16816(cfr[mi][2 * nj],     ah[mi], bl[nj]);
                    mma16816(cfr[mi][2 * nj + 1], ah[mi], bl[nj] + 2);
                }
            #pragma unroll
            for (int mi = 0; mi < 4; mi++)
                #pragma unroll
                for (int nj = 0; nj < 2; nj++) {
                    mma16816(cfr[mi][2 * nj],     al[mi], bh[nj]);
                    mma16816(cfr[mi][2 * nj + 1], al[mi], bh[nj] + 2);
                }
        }
        __syncthreads();
    }

    #pragma unroll
    for (int mi = 0; mi < 4; mi++)
        #pragma unroll
        for (int h = 0; h < 2; h++) {
            const size_t b = (size_t)(b0 + mi * 16 + gid + 8 * h);
            #pragma unroll
            for (int ni = 0; ni < 4; ni++) {
                const int n = nb + ni * 8 + 2 * tig;
                float v0a = cfr[mi][ni][2 * h]     + __ldg(bias + n);
                float v0b = cfr[mi][ni][2 * h + 1] + __ldg(bias + n + 1);
                st2(Oh, Ol, b * 512 + n, 2.0f * tanhf(v0a), 2.0f * tanhf(v0b));
                st2(Oh, Ol, b * 512 + 256 + n,
                    v0a + 0.1f * __ldg(qn + n), v0b + 0.1f * __ldg(qn + n + 1));
            }
        }
}

// ======================= fused per-layer kernel =======================
// Phase 1: z1[64x256] = E_l @ R[b-tile]   (K=512)      -> staged to smem (bf16 pair)
// Phase 2: acc = B0_l @ z1                (K=256, z1 A-operand from smem)
// Epilogue: z0 = r0 - acc;  LAST=0: R <- [z1 + tanh(z0); z0 + 0.1 q_next]
//                           LAST=1: v0 <- z0
#define BUF_SZ    40960                      // phase buffer: 8KB A + 32KB B
#define Z1H_OFF   BUF_SZ                     // 8 chunks x 4KB
#define Z1L_OFF   (BUF_SZ + 32768)
#define FUSED_SMEM (BUF_SZ + 65536)          // 104 KB

template <int LAST>
__global__ void __launch_bounds__(256, 2)
fusedLayer(const __nv_bfloat16* __restrict__ Rh, const __nv_bfloat16* __restrict__ Rl,
           const __nv_bfloat16* __restrict__ Eh, const __nv_bfloat16* __restrict__ El,
           const __nv_bfloat16* __restrict__ B0h, const __nv_bfloat16* __restrict__ B0l,
           const float* __restrict__ qn,
           __nv_bfloat16* __restrict__ Wrh, __nv_bfloat16* __restrict__ Wrl,
           __nv_bfloat16* __restrict__ v0h, __nv_bfloat16* __restrict__ v0l)
{
    extern __shared__ __align__(128) unsigned char smem[];
    const uint32_t sb = (uint32_t)__cvta_generic_to_shared(smem);

    const int tid  = threadIdx.x;
    const int warp = tid >> 5, lane = tid & 31;
    const int gid  = lane >> 2, tig = lane & 3;
    const int b0   = blockIdx.x * 64;
    const int nb   = warp * 32;

    // ---------------- Phase 1: z1 = E @ R, K = 512 ----------------
    {
        float cfr[4][4][4] = {};
        for (int ch = 0; ch < 16; ch++) {
            const int k0 = ch << 5;
            for (int i = tid; i < 2560; i += 256) {
                const __nv_bfloat16* src; unsigned char* dst;
                if (i < 512) {
                    int part = i >> 8, idx = i & 255, row = idx >> 2, g = idx & 3;
                    src = (part ? Rl : Rh) + (size_t)(b0 + row) * 512 + k0 + g * 8;
                    dst = smem + part * A_SZ + swb(row, g);
                } else {
                    int j = i - 512;
                    int part = j >> 10, idx = j & 1023, row = idx >> 2, g = idx & 3;
                    src = (part ? El : Eh) + (size_t)row * 512 + k0 + g * 8;
                    dst = smem + 2 * A_SZ + part * B_SZ + swb(row, g);
                }
                *(uint4*)dst = *(const uint4*)src;
            }
            __syncthreads();

            const uint32_t sAh = sb, sAl = sb + A_SZ;
            const uint32_t sBh = sb + 2 * A_SZ, sBl = sb + 2 * A_SZ + B_SZ;
            #pragma unroll
            for (int ks = 0; ks < 2; ks++) {
                uint32_t ah[4][4], al[4][4], bh[2][4], bl[2][4];
                const int arow = (lane & 15), agr = ks * 2 + (lane >> 4);
                #pragma unroll
                for (int mi = 0; mi < 4; mi++) {
                    uint32_t off = swb(mi * 16 + arow, agr);
                    ldsm4(ah[mi], sAh + off); ldsm4(al[mi], sAl + off);
                }
                const int brow = (lane & 7) + ((lane >> 4) << 3);
                const int bgr  = ks * 2 + ((lane >> 3) & 1);
                #pragma unroll
                for (int nj = 0; nj < 2; nj++) {
                    uint32_t off = swb(nb + nj * 16 + brow, bgr);
                    ldsm4(bh[nj], sBh + off); ldsm4(bl[nj], sBl + off);
                }
                #pragma unroll
                for (int mi = 0; mi < 4; mi++)
                    #pragma unroll
                    for (int nj = 0; nj < 2; nj++) {
                        mma16816(cfr[mi][2 * nj],     ah[mi], bh[nj]);
                        mma16816(cfr[mi][2 * nj + 1], ah[mi], bh[nj] + 2);
                    }
                #pragma unroll
                for (int mi = 0; mi < 4; mi++)
                    #pragma unroll
                    for (int nj = 0; nj < 2; nj++) {
                        mma16816(cfr[mi][2 * nj],     ah[mi], bl[nj]);
                        mma16816(cfr[mi][2 * nj + 1], ah[mi], bl[nj] + 2);
                    }
                #pragma unroll
                for (int mi = 0; mi < 4; mi++)
                    #pragma unroll
                    for (int nj = 0; nj < 2; nj++) {
                        mma16816(cfr[mi][2 * nj],     al[mi], bh[nj]);
                        mma16816(cfr[mi][2 * nj + 1], al[mi], bh[nj] + 2);
                    }
            }
            __syncthreads();
        }

        // stage z1 to smem in A-chunk ldmatrix format (warp w -> chunk w)
        const uint32_t zh = sb + Z1H_OFF + warp * 4096;
        const uint32_t zl = sb + Z1L_OFF + warp * 4096;
        #pragma unroll
        for (int mi = 0; mi < 4; mi++)
            #pragma unroll
            for (int h = 0; h < 2; h++) {
                const int row = mi * 16 + gid + 8 * h;
                #pragma unroll
                for (int ni = 0; ni < 4; ni++) {
                    float x0 = cfr[mi][ni][2 * h], x1 = cfr[mi][ni][2 * h + 1];
                    uint32_t hp = packbf(x0, x1);
                    __nv_bfloat162* hv = (__nv_bfloat162*)&hp;
                    uint32_t lp = packbf(x0 - __bfloat162float(hv->x),
                                         x1 - __bfloat162float(hv->y));
                    uint32_t off = swb(row, ni) + 4 * tig;
                    asm volatile("st.shared.b32 [%0], %1;" :: "r"(zh + off), "r"(hp));
                    asm volatile("st.shared.b32 [%0], %1;" :: "r"(zl + off), "r"(lp));
                }
            }
    }
    __syncthreads();

    // ---------------- Phase 2: acc = B0 @ z1, K = 256 ----------------
    float cfr[4][4][4] = {};
    for (int ch = 0; ch < 8; ch++) {
        const int k0 = ch << 5;
        for (int i = tid; i < 2048; i += 256) {
            int part = i >> 10, idx = i & 1023, row = idx >> 2, g = idx & 3;
            const __nv_bfloat16* src = (part ? B0l : B0h) + (size_t)row * 256 + k0 + g * 8;
            *(uint4*)(smem + part * B_SZ + swb(row, g)) = *(const uint4*)src;
        }
        __syncthreads();

        const uint32_t sAh = sb + Z1H_OFF + ch * 4096;
        const uint32_t sAl = sb + Z1L_OFF + ch * 4096;
        const uint32_t sBh = sb, sBl = sb + B_SZ;
        #pragma unroll
        for (int ks = 0; ks < 2; ks++) {
            uint32_t ah[4][4], al[4][4], bh[2][4], bl[2][4];
            const int arow = (lane & 15), agr = ks * 2 + (lane >> 4);
            #pragma unroll
            for (int mi = 0; mi < 4; mi++) {
                uint32_t off = swb(mi * 16 + arow, agr);
                ldsm4(ah[mi], sAh + off); ldsm4(al[mi], sAl + off);
            }
            const int brow = (lane & 7) + ((lane >> 4) << 3);
            const int bgr  = ks * 2 + ((lane >> 3) & 1);
            #pragma unroll
            for (int nj = 0; nj < 2; nj++) {
                uint32_t off = swb(nb + nj * 16 + brow, bgr);
                ldsm4(bh[nj], sBh + off); ldsm4(bl[nj], sBl + off);
            }
            #pragma unroll
            for (int mi = 0; mi < 4; mi++)
                #pragma unroll
                for (int nj = 0; nj < 2; nj++) {
                    mma16816(cfr[mi][2 * nj],     ah[mi], bh[nj]);
                    mma16816(cfr[mi][2 * nj + 1], ah[mi], bh[nj] + 2);
                }
            #pragma unroll
            for (int mi = 0; mi < 4; mi++)
                #pragma unroll
                for (int nj = 0; nj < 2; nj++) {
                    mma16816(cfr[mi][2 * nj],     ah[mi], bl[nj]);
                    mma16816(cfr[mi][2 * nj + 1], ah[mi], bl[nj] + 2);
                }
            #pragma unroll
            for (int mi = 0; mi < 4; mi++)
                #pragma unroll
                for (int nj = 0; nj < 2; nj++) {
                    mma16816(cfr[mi][2 * nj],     al[mi], bh[nj]);
                    mma16816(cfr[mi][2 * nj + 1], al[mi], bh[nj] + 2);
                }
        }
        __syncthreads();
    }

    // ---------------- epilogue ----------------
    const uint32_t zh = sb + Z1H_OFF + warp * 4096;
    const uint32_t zl = sb + Z1L_OFF + warp * 4096;
    #pragma unroll
    for (int mi = 0; mi < 4; mi++)
        #pragma unroll
        for (int h = 0; h < 2; h++) {
            const int row = mi * 16 + gid + 8 * h;
            const size_t b = (size_t)(b0 + row);
            #pragma unroll
            for (int ni = 0; ni < 4; ni++) {
                const int n = nb + ni * 8 + 2 * tig;
                float r0a, r0b;
                ld2(Rh, Rl, b * 512 + 256 + n, r0a, r0b);
                float z0a = r0a - cfr[mi][ni][2 * h];
                float z0b = r0b - cfr[mi][ni][2 * h + 1];
                if (LAST) {
                    st2(v0h, v0l, b * 256 + n, z0a, z0b);
                } else {
                    uint32_t off = swb(row, ni) + 4 * tig;
                    uint32_t hp, lp;
                    asm volatile("ld.shared.b32 %0, [%1];" : "=r"(hp) : "r"(zh + off));
                    asm volatile("ld.shared.b32 %0, [%1];" : "=r"(lp) : "r"(zl + off));
                    __nv_bfloat162 hv = *(__nv_bfloat162*)&hp;
                    __nv_bfloat162 lv = *(__nv_bfloat162*)&lp;
                    float z1a = __bfloat162float(hv.x) + __bfloat162float(lv.x);
                    float z1b = __bfloat162float(hv.y) + __bfloat162float(lv.y);
                    st2(Wrh, Wrl, b * 512 + n, z1a + tanhf(z0a), z1b + tanhf(z0b));
                    st2(Wrh, Wrl, b * 512 + 256 + n,
                        z0a + 0.1f * __ldg(qn + n), z0b + 0.1f * __ldg(qn + n + 1));
                }
            }
        }
}

// ======================= split kernels =======================
__global__ void xsplit(const float* __restrict__ x,
                       __nv_bfloat16* __restrict__ xh, __nv_bfloat16* __restrict__ xl) {
    size_t bb = blockIdx.x;
    for (int d = threadIdx.x; d < KX; d += 256) {
        float v = (d < INDIM) ? x[bb * INDIM + d] : 0.0f;
        __nv_bfloat16 h = __float2bfloat16(v);
        xh[bb * KX + d] = h;
        xl[bb * KX + d] = __float2bfloat16(v - __bfloat162float(h));
    }
}

__global__ void wtsplit(const float* __restrict__ Win,
                        __nv_bfloat16* __restrict__ wh, __nv_bfloat16* __restrict__ wl) {
    int i = blockIdx.x;
    for (int d = threadIdx.x; d < KX; d += 256) {
        float v = (d < INDIM) ? Win[(size_t)d * U + i] : 0.0f;
        __nv_bfloat16 h = __float2bfloat16(v);
        wh[(size_t)i * KX + d] = h;
        wl[(size_t)i * KX + d] = __float2bfloat16(v - __bfloat162float(h));
    }
}

__global__ void splitArr(const float* __restrict__ s,
                         __nv_bfloat16* __restrict__ h, __nv_bfloat16* __restrict__ l, int n) {
    int i = blockIdx.x * 256 + threadIdx.x;
    if (i < n) {
        float v = s[i];
        __nv_bfloat16 hh = __float2bfloat16(v);
        h[i] = hh;
        l[i] = __float2bfloat16(v - __bfloat162float(hh));
    }
}

// ======================= fp32 precompute path (Newton-Schulz) =======================
template <int TA, int TB>
__global__ void gemm256(const float* __restrict__ Aall, const float* __restrict__ Ball,
                        float* __restrict__ Call, int ldc, int cofs,
                        float alpha, float dval)
{
    const float* A  = Aall + (size_t)blockIdx.z * (U * U);
    const float* Bm = Ball + (size_t)blockIdx.z * (U * U);
    float*       C  = Call + (size_t)blockIdx.z * (U * ldc);

    __shared__ float As[16][68];
    __shared__ float Bs[16][68];

    int t = threadIdx.x, tx = t & 15, ty = t >> 4;
    int i0 = blockIdx.y * 64, j0 = blockIdx.x * 64;
    float acc[4][4] = {};

    for (int k0 = 0; k0 < U; k0 += 16) {
        if (TA == 0) {
            int i = t >> 2, k4 = (t & 3) * 4;
            float4 v = *(const float4*)&A[(i0 + i) * U + k0 + k4];
            As[k4 + 0][i] = v.x; As[k4 + 1][i] = v.y; As[k4 + 2][i] = v.z; As[k4 + 3][i] = v.w;
        } else {
            int k = t >> 4, i4 = (t & 15) * 4;
            float4 v = *(const float4*)&A[(k0 + k) * U + i0 + i4];
            As[k][i4 + 0] = v.x; As[k][i4 + 1] = v.y; As[k][i4 + 2] = v.z; As[k][i4 + 3] = v.w;
        }
        if (TB == 0) {
            int k = t >> 4, j4 = (t & 15) * 4;
            float4 v = *(const float4*)&Bm[(k0 + k) * U + j0 + j4];
            Bs[k][j4 + 0] = v.x; Bs[k][j4 + 1] = v.y; Bs[k][j4 + 2] = v.z; Bs[k][j4 + 3] = v.w;
        } else {
            int j = t >> 2, k4 = (t & 3) * 4;
            float4 v = *(const float4*)&Bm[(j0 + j) * U + k0 + k4];
            Bs[k4 + 0][j] = v.x; Bs[k4 + 1][j] = v.y; Bs[k4 + 2][j] = v.z; Bs[k4 + 3][j] = v.w;
        }
        __syncthreads();
        #pragma unroll
        for (int k = 0; k < 16; k++) {
            float a[4], b[4];
            #pragma unroll
            for (int rr = 0; rr < 4; rr++) a[rr] = As[k][ty * 4 + rr];
            #pragma unroll
            for (int cci = 0; cci < 4; cci++) b[cci] = Bs[k][tx * 4 + cci];
            #pragma unroll
            for (int rr = 0; rr < 4; rr++)
                #pragma unroll
                for (int cci = 0; cci < 4; cci++)
                    acc[rr][cci] += a[rr] * b[cci];
        }
        __syncthreads();
    }
    #pragma unroll
    for (int rr = 0; rr < 4; rr++) {
        int gi = i0 + ty * 4 + rr;
        #pragma unroll
        for (int cci = 0; cci < 4; cci++) {
            int gj = j0 + tx * 4 + cci;
            C[gi * ldc + cofs + gj] = alpha * acc[rr][cci] + ((gi == gj) ? dval : 0.0f);
        }
    }
}

__global__ void initX(const float* __restrict__ Mall, float* __restrict__ Xall) {
    int l = blockIdx.x;
    const float* M = Mall + (size_t)l * U * U;
    float*       X = Xall + (size_t)l * U * U;
    int t = threadIdx.x;
    int j = t & 255, part = t >> 8;

    float s = 0.0f;
    #pragma unroll 8
    for (int r = part * 64; r < part * 64 + 64; r++) s += fabsf(M[r * U + j]);

    __shared__ float red[1024];
    red[t] = s; __syncthreads();
    if (part == 0) red[j] = red[j] + red[j + 256] + red[j + 512] + red[j + 768];
    __syncthreads();
    for (int o = 128; o > 0; o >>= 1) {
        if (t < o) red[t] = fmaxf(red[t], red[t + o]);
        __syncthreads();
    }
    float c = 2.0f / (2.0f + red[0]);
    for (int e = t; e < U * U; e += 1024)
        X[e] = ((e >> 8) == (e & 255)) ? c : 0.0f;
}

__global__ void copyE(const float* __restrict__ X, float* __restrict__ E) {
    int idx = blockIdx.x * blockDim.x + threadIdx.x;
    int l = idx >> 16, rr = (idx >> 8) & 255, cc = idx & 255;
    E[(size_t)l * U * 512 + rr * 512 + cc] = X[idx];
}

// ======================= output projection =======================
__global__ void outKernel(const __nv_bfloat16* __restrict__ v0h,
                          const __nv_bfloat16* __restrict__ v0l,
                          const float* __restrict__ Wout, const float* __restrict__ bout,
                          float* __restrict__ out) {
    __shared__ float Ws[U * ODIM];
    __shared__ float bs[ODIM];
    int t = threadIdx.x;
    for (int j = t; j < U * ODIM; j += 256) Ws[j] = Wout[j];
    if (t < ODIM) bs[t] = bout[t];
    __syncthreads();

    int w = t >> 5, lane = t & 31;
    size_t b = (size_t)blockIdx.x * 8 + w;
    float acc[ODIM] = {};
    for (int n = lane; n < U; n += 32) {
        float v = __bfloat162float(v0h[b * U + n]) + __bfloat162float(v0l[b * U + n]);
        #pragma unroll
        for (int o = 0; o < ODIM; o++) acc[o] += v * Ws[n * ODIM + o];
    }
    #pragma unroll
    for (int o = 0; o < ODIM; o++)
        #pragma unroll
        for (int s = 16; s > 0; s >>= 1) acc[o] += __shfl_xor_sync(0xFFFFFFFFu, acc[o], s);
    if (lane < ODIM) out[b * ODIM + lane] = acc[lane] + bs[lane];
}

// ======================= launch =======================
extern "C" void kernel_launch(void* const* d_in, const int* in_sizes, int n_in,
                              void* d_out, int out_size)
{
    (void)in_sizes; (void)n_in; (void)out_size;
    const float* x     = (const float*)d_in[0];
    const float* W_in  = (const float*)d_in[1];
    const float* b_in  = (const float*)d_in[2];
    const float* B0    = (const float*)d_in[3];
    const float* q     = (const float*)d_in[4];
    const float* W_out = (const float*)d_in[5];
    const float* b_out = (const float*)d_in[6];
    float* out = (float*)d_out;

    unsigned char* pool;
    cudaGetSymbolAddress((void**)&pool, g_pool);
    __nv_bfloat16* xh  = (__nv_bfloat16*)(pool + O_XH);
    __nv_bfloat16* xl  = (__nv_bfloat16*)(pool + O_XL);
    __nv_bfloat16* wth = (__nv_bfloat16*)(pool + O_WTH);
    __nv_bfloat16* wtl = (__nv_bfloat16*)(pool + O_WTL);
    __nv_bfloat16* Rh  = (__nv_bfloat16*)(pool + O_RH);
    __nv_bfloat16* Rl  = (__nv_bfloat16*)(pool + O_RL);
    __nv_bfloat16* v0h = (__nv_bfloat16*)(pool + O_V0H);
    __nv_bfloat16* v0l = (__nv_bfloat16*)(pool + O_V0L);
    __nv_bfloat16* Eh  = (__nv_bfloat16*)(pool + O_EH);
    __nv_bfloat16* El  = (__nv_bfloat16*)(pool + O_EL);
    __nv_bfloat16* Bh  = (__nv_bfloat16*)(pool + O_BH);
    __nv_bfloat16* Bl  = (__nv_bfloat16*)(pool + O_BL);
    float* pM  = (float*)(pool + O_M);
    float* pXa = (float*)(pool + O_XA);
    float* pXb = (float*)(pool + O_XB);
    float* pT  = (float*)(pool + O_T);
    float* pE  = (float*)(pool + O_EF);

    static int smem_set = 0;
    if (!smem_set) {
        cudaFuncSetAttribute(fusedLayer<0>, cudaFuncAttributeMaxDynamicSharedMemorySize, FUSED_SMEM);
        cudaFuncSetAttribute(fusedLayer<1>, cudaFuncAttributeMaxDynamicSharedMemorySize, FUSED_SMEM);
        smem_set = 1;
    }

    // ---- operand splits ----
    xsplit<<<BATCHN, 256>>>(x, xh, xl);
    wtsplit<<<U, 256>>>(W_in, wth, wtl);

    // ---- Newton-Schulz inverse precompute (fp32) ----
    dim3 gs(4, 4, NL);
    gemm256<1, 0><<<gs, 256>>>(B0, B0, pM, U, 0, 1.0f, 2.0f);       // M = 2I + B^T B
    initX<<<NL, 1024>>>(pM, pXa);
    float* Xc = pXa; float* Xn = pXb;
    for (int it = 0; it < 6; it++) {
        gemm256<0, 0><<<gs, 256>>>(pM, Xc, pT, U, 0, -1.0f, 2.0f);  // T = 2I - M X
        gemm256<0, 0><<<gs, 256>>>(Xc, pT, Xn, U, 0, 1.0f, 0.0f);   // X <- X T
        float* tmp = Xc; Xc = Xn; Xn = tmp;
    }
    copyE<<<NL * U * U / 256, 256>>>(Xc, pE);                       // E[:, :256] = Minv
    gemm256<0, 1><<<gs, 256>>>(Xc, B0, pE, 2 * U, U, 1.0f, 0.0f);   // E[:, 256:] = Minv B^T
    splitArr<<<(NL * U * 2 * U + 255) / 256, 256>>>(pE, Eh, El, NL * U * 2 * U);
    splitArr<<<(NL * U * U + 255) / 256, 256>>>(B0, Bh, Bl, NL * U * U);

    // ---- input layer: R_0 from x @ W_in + b_in ----
    inGemm<<<BATCHN / 64, 256>>>(xh, xl, wth, wtl, b_in, q, Rh, Rl);

    // ---- 8 implicit layers: ONE fused kernel each ----
    for (int l = 0; l < NL; l++) {
        const __nv_bfloat16* ehl = Eh + (size_t)l * U * 2 * U;
        const __nv_bfloat16* ell = El + (size_t)l * U * 2 * U;
        const __nv_bfloat16* bhl = Bh + (size_t)l * U * U;
        const __nv_bfloat16* bll = Bl + (size_t)l * U * U;
        if (l < NL - 1) {
            fusedLayer<0><<<BATCHN / 64, 256, FUSED_SMEM>>>(Rh, Rl, ehl, ell, bhl, bll,
                                                            q + (size_t)(l + 1) * U,
                                                            Rh, Rl, nullptr, nullptr);
        } else {
            fusedLayer<1><<<BATCHN / 64, 256, FUSED_SMEM>>>(Rh, Rl, ehl, ell, bhl, bll,
                                                            nullptr, nullptr, nullptr,
                                                            v0h, v0l);
        }
    }

    outKernel<<<BATCHN / 8, 256>>>(v0h, v0l, W_out, b_out, out);
}